// round 10
// baseline (speedup 1.0000x reference)
#include <cuda_runtime.h>
#include <cuda_bf16.h>
#include <math.h>
#include <stdint.h>

#define B_DIM 2048
#define D_DIM 512
#define C_DIM 32000
#define SCALE_F 32.0f
#define MARGIN_F 16.0f
#define INV254 (1.0f / 254.0f)

// ---------------- scratch (device globals; no allocation allowed) ----------
__device__ float g_invnx[B_DIM];
__device__ float g_invnw[C_DIM];
__device__ float g_sxx[B_DIM];
__device__ float g_sxw[C_DIM];
__device__ int   g_tgt[B_DIM];
__device__ __align__(16) char g_xq[(size_t)B_DIM * D_DIM];
__device__ __align__(16) char g_xr[(size_t)B_DIM * D_DIM];
__device__ __align__(16) char g_wq[(size_t)C_DIM * D_DIM];
__device__ __align__(16) char g_wr[(size_t)C_DIM * D_DIM];

// ---------------- helpers ----------------------------------------------------
static __device__ __forceinline__ uint32_t smem_u32(const void* p) {
    uint32_t a;
    asm("{ .reg .u64 t; cvta.to.shared.u64 t, %1; cvt.u32.u64 %0, t; }" : "=r"(a) : "l"(p));
    return a;
}
static __device__ __forceinline__ void cp16(uint32_t dst, const void* src) {
    asm volatile("cp.async.cg.shared.global [%0], [%1], 16;" :: "r"(dst), "l"(src) : "memory");
}
static __device__ __forceinline__ void ldsm_x4(uint32_t* r, uint32_t addr) {
    asm volatile("ldmatrix.sync.aligned.m8n8.x4.shared.b16 {%0,%1,%2,%3}, [%4];"
                 : "=r"(r[0]), "=r"(r[1]), "=r"(r[2]), "=r"(r[3]) : "r"(addr));
}
static __device__ __forceinline__ void mma_s8(int* d, const uint32_t* a,
                                              uint32_t b0, uint32_t b1) {
    asm volatile(
        "mma.sync.aligned.m16n8k32.row.col.s32.s8.s8.s32 "
        "{%0,%1,%2,%3}, {%4,%5,%6,%7}, {%8,%9}, {%0,%1,%2,%3};"
        : "+r"(d[0]), "+r"(d[1]), "+r"(d[2]), "+r"(d[3])
        : "r"(a[0]), "r"(a[1]), "r"(a[2]), "r"(a[3]), "r"(b0), "r"(b1));
}
// 64B-row swizzle: 16B chunk c in row -> c ^ ((row>>1)&3). Conflict-free for ldmatrix.
static __device__ __forceinline__ uint32_t swz64(uint32_t row, uint32_t c) {
    return row * 64u + ((c ^ ((row >> 1) & 3u)) << 4);
}

// ---------------- fused rownorm + int8 two-level quantize --------------------
// One block (128 threads) per row of 512 floats; each thread one float4.
__global__ void prep_i8(const float* __restrict__ src,
                        float* __restrict__ invn, float* __restrict__ sxs,
                        char* __restrict__ q8, char* __restrict__ r8) {
    int row = blockIdx.x;
    size_t base = (size_t)row * D_DIM + threadIdx.x * 4;
    float4 v = *reinterpret_cast<const float4*>(src + base);
    float f[4] = {v.x, v.y, v.z, v.w};

    float am = fmaxf(fmaxf(fabsf(f[0]), fabsf(f[1])), fmaxf(fabsf(f[2]), fabsf(f[3])));
    float ss = f[0]*f[0] + f[1]*f[1] + f[2]*f[2] + f[3]*f[3];
    #pragma unroll
    for (int o = 16; o > 0; o >>= 1) {
        am = fmaxf(am, __shfl_xor_sync(0xffffffffu, am, o));
        ss += __shfl_xor_sync(0xffffffffu, ss, o);
    }
    __shared__ float wm_[4], ws_[4], s_sx;
    int lane = threadIdx.x & 31, w = threadIdx.x >> 5;
    if (lane == 0) { wm_[w] = am; ws_[w] = ss; }
    __syncthreads();
    if (threadIdx.x == 0) {
        float amax = fmaxf(fmaxf(wm_[0], wm_[1]), fmaxf(wm_[2], wm_[3]));
        float sum  = ws_[0] + ws_[1] + ws_[2] + ws_[3];
        invn[row] = 1.0f / fmaxf(sqrtf(sum), 1e-12f);
        float sx = fmaxf(amax, 1e-30f) * (1.0f / 127.0f);
        sxs[row] = sx;
        s_sx = sx;
    }
    __syncthreads();
    float sx = s_sx, inv_sx = 1.0f / sx;

    char q[4], r[4];
    #pragma unroll
    for (int i = 0; i < 4; i++) {
        int qi = __float2int_rn(f[i] * inv_sx);
        float res = f[i] - sx * (float)qi;
        int ri = __float2int_rn(res * (254.0f * inv_sx));
        q[i] = (char)qi;
        r[i] = (char)ri;
    }
    *reinterpret_cast<uint32_t*>(q8 + base) = *reinterpret_cast<uint32_t*>(q);
    *reinterpret_cast<uint32_t*>(r8 + base) = *reinterpret_cast<uint32_t*>(r);
}

// ---------------- decode targets (proven global probe) ----------------------
__global__ void decode_targets(const void* __restrict__ targets,
                               int* __restrict__ tgt) {
    const int tid = threadIdx.x;  // one block, 1024 threads
    const int* ti = reinterpret_cast<const int*>(targets);
    int odd = ti[2 * tid + 1];
    int any_nonzero = __syncthreads_or(odd != 0);
    const bool is64 = (any_nonzero == 0);
    #pragma unroll
    for (int r = 0; r < 2; r++) {
        int b = tid + r * 1024;
        int t;
        if (is64) t = (int)reinterpret_cast<const long long*>(targets)[b];
        else      t = ti[b];
        tgt[b] = t;
    }
}

// ---------------- GEMM: int8 mma.sync m16n8k32, 2 int accumulators ----------
// CTA tile 128(m) x 128(n), BK = 64 int8 (64B rows). 512 threads, 16 warps
// (4m x 4n), warp tile m32 x n32. 4-stage cp.async pipeline, 32KB/stage.
// smem: [0..512) row scale (sx*invnx*32), [512..1024) col scale (sw*invnw),
//       [1024..1536) targets, [2048 + s*32768): stage = Aq 8K|Ar 8K|Bq 8K|Br 8K
#define STAGE_I 32768u
#define SMEM_TOTAL_I (2048u + 4u * STAGE_I)

__global__ void __launch_bounds__(512, 1)
gemm_kernel(float* __restrict__ out_loss, float* __restrict__ out_pred) {
    extern __shared__ __align__(128) unsigned char smem[];
    const uint32_t sb = smem_u32(smem);
    const uint32_t st0 = sb + 2048u;
    const int tid = threadIdx.x;
    const int wid = tid >> 5, lane = tid & 31;
    const int wm = wid & 3, wn = wid >> 2;    // 4m x 4n warp grid

    const int bid = blockIdx.x;          // m-fastest: consecutive CTAs share W panel
    const int mt = bid & 15, nt = bid >> 4;
    const int m0 = mt * 128, n0 = nt * 128;

    float* s_rx = reinterpret_cast<float*>(smem);
    float* s_cw = reinterpret_cast<float*>(smem + 512);
    int*   s_tg = reinterpret_cast<int*>(smem + 1024);
    if (tid < 128) {
        s_rx[tid] = g_sxx[m0 + tid] * g_invnx[m0 + tid] * SCALE_F;
        s_cw[tid] = g_sxw[n0 + tid] * g_invnw[n0 + tid];
        s_tg[tid] = g_tgt[m0 + tid] - n0;
    }
    __syncthreads();

    // ---- g2s issue of one K-chunk (64 int8) into stage s: 4 cp16/thread ----
    auto issue = [&](int s, int chunk) {
        uint32_t st = st0 + (uint32_t)s * STAGE_I;
        int k0 = chunk * 64;
        uint32_t row = (uint32_t)tid >> 2, c = (uint32_t)tid & 3;
        size_t ga = (size_t)(m0 + row) * D_DIM + k0 + c * 16;
        uint32_t da = st + swz64(row, c);
        cp16(da,         g_xq + ga);
        cp16(da + 8192u, g_xr + ga);
        size_t gb = (size_t)(n0 + row) * D_DIM + k0 + c * 16;
        uint32_t db = st + 16384u + swz64(row, c);
        cp16(db,         g_wq + gb);
        cp16(db + 8192u, g_wr + gb);
        asm volatile("cp.async.commit_group;" ::: "memory");
    };

    int acc1[2][4][4], acc2[2][4][4];
    #pragma unroll
    for (int i = 0; i < 2; i++)
        #pragma unroll
        for (int j = 0; j < 4; j++)
            #pragma unroll
            for (int q = 0; q < 4; q++) { acc1[i][j][q] = 0; acc2[i][j][q] = 0; }

    issue(0, 0); issue(1, 1); issue(2, 2); issue(3, 3);

    const uint32_t arow = lane & 15;      // ldmatrix row within 16
    const uint32_t akq  = lane >> 4;      // 16B-chunk select (0/1) within k32

    #pragma unroll 1
    for (int c = 0; c < 8; c++) {
        if      (c <= 4) asm volatile("cp.async.wait_group 3;" ::: "memory");
        else if (c == 5) asm volatile("cp.async.wait_group 2;" ::: "memory");
        else if (c == 6) asm volatile("cp.async.wait_group 1;" ::: "memory");
        else             asm volatile("cp.async.wait_group 0;" ::: "memory");
        __syncthreads();

        uint32_t st = st0 + (uint32_t)(c & 3) * STAGE_I;
        #pragma unroll
        for (int s = 0; s < 2; s++) {     // 2 k32 steps per 64-chunk
            uint32_t ck = 2 * s + akq;    // 16B chunk index within row
            uint32_t aq[2][4], ar[2][4];
            #pragma unroll
            for (int mi = 0; mi < 2; mi++) {
                uint32_t row = (uint32_t)(wm * 32 + mi * 16) + arow;
                uint32_t a = st + swz64(row, ck);
                ldsm_x4(aq[mi], a);
                ldsm_x4(ar[mi], a + 8192u);
            }
            #pragma unroll
            for (int nj = 0; nj < 2; nj++) {
                uint32_t bq[4], br[4];
                uint32_t row = (uint32_t)(wn * 32 + nj * 16) + arow;
                uint32_t b = st + 16384u + swz64(row, ck);
                ldsm_x4(bq, b);
                ldsm_x4(br, b + 8192u);
                #pragma unroll
                for (int mi = 0; mi < 2; mi++)
                    #pragma unroll
                    for (int sel = 0; sel < 2; sel++) {
                        int j = nj * 2 + sel;
                        mma_s8(acc1[mi][j], aq[mi], bq[sel], bq[2 + sel]);
                        mma_s8(acc2[mi][j], aq[mi], br[sel], br[2 + sel]);
                        mma_s8(acc2[mi][j], ar[mi], bq[sel], bq[2 + sel]);
                    }
            }
        }
        __syncthreads();
        if (c + 4 < 8) issue(c & 3, c + 4);
    }

    // ---- epilogue: v = (acc1 + acc2/254)*sx*sw*invnx*invnw*32; fused margin --
    const int gr = lane >> 2, gc = lane & 3;
    #pragma unroll
    for (int mi = 0; mi < 2; mi++) {
        int rl = wm * 32 + mi * 16 + gr;      // local rows rl, rl+8
        float rx0 = s_rx[rl], rx1 = s_rx[rl + 8];
        int t0 = s_tg[rl], t1 = s_tg[rl + 8];
        size_t off0 = (size_t)(m0 + rl) * C_DIM + n0;
        size_t off1 = off0 + (size_t)8 * C_DIM;
        #pragma unroll
        for (int j = 0; j < 4; j++) {
            int col = wn * 32 + j * 8 + gc * 2;
            float cw0 = s_cw[col], cw1 = s_cw[col + 1];
            float2 v0, v1;
            v0.x = ((float)acc1[mi][j][0] + (float)acc2[mi][j][0] * INV254) * rx0 * cw0;
            v0.y = ((float)acc1[mi][j][1] + (float)acc2[mi][j][1] * INV254) * rx0 * cw1;
            v1.x = ((float)acc1[mi][j][2] + (float)acc2[mi][j][2] * INV254) * rx1 * cw0;
            v1.y = ((float)acc1[mi][j][3] + (float)acc2[mi][j][3] * INV254) * rx1 * cw1;
            *reinterpret_cast<float2*>(out_pred + off0 + col) = v0;
            *reinterpret_cast<float2*>(out_pred + off1 + col) = v1;
            float2 u0 = v0, u1 = v1;
            if (t0 == col)     u0.x -= MARGIN_F;
            if (t0 == col + 1) u0.y -= MARGIN_F;
            if (t1 == col)     u1.x -= MARGIN_F;
            if (t1 == col + 1) u1.y -= MARGIN_F;
            *reinterpret_cast<float2*>(out_loss + off0 + col) = u0;
            *reinterpret_cast<float2*>(out_loss + off1 + col) = u1;
        }
    }
}

// ---------------------------------------------------------------------------
extern "C" void kernel_launch(void* const* d_in, const int* in_sizes, int n_in,
                              void* d_out, int out_size) {
    const float* x  = (const float*)d_in[0];
    const float* w  = (const float*)d_in[1];
    const void*  tg = d_in[2];

    float* out_loss = (float*)d_out;
    float* out_pred = out_loss + (size_t)B_DIM * C_DIM;

    float *invnx, *invnw, *sxx, *sxw;
    int* tgt;
    char *xq, *xr, *wq, *wr;
    cudaGetSymbolAddress((void**)&invnx, g_invnx);
    cudaGetSymbolAddress((void**)&invnw, g_invnw);
    cudaGetSymbolAddress((void**)&sxx, g_sxx);
    cudaGetSymbolAddress((void**)&sxw, g_sxw);
    cudaGetSymbolAddress((void**)&tgt, g_tgt);
    cudaGetSymbolAddress((void**)&xq, g_xq);
    cudaGetSymbolAddress((void**)&xr, g_xr);
    cudaGetSymbolAddress((void**)&wq, g_wq);
    cudaGetSymbolAddress((void**)&wr, g_wr);

    decode_targets<<<1, 1024>>>(tg, tgt);
    prep_i8<<<B_DIM, 128>>>(x, invnx, sxx, xq, xr);
    prep_i8<<<C_DIM, 128>>>(w, invnw, sxw, wq, wr);

    cudaFuncSetAttribute(gemm_kernel, cudaFuncAttributeMaxDynamicSharedMemorySize, SMEM_TOTAL_I);
    gemm_kernel<<<4000, 512, SMEM_TOTAL_I>>>(out_loss, out_pred);
}

// round 11
// speedup vs baseline: 5.0527x; 5.0527x over previous
#include <cuda_runtime.h>
#include <cuda_fp16.h>
#include <math.h>
#include <stdint.h>

#define B_DIM 2048
#define D_DIM 512
#define C_DIM 32000
#define SCALE_F 32.0f
#define MARGIN_F 16.0f

// ---------------- scratch (device globals; no allocation allowed) ----------
__device__ int g_tgt[B_DIM];
__device__ __align__(16) __half g_xh[(size_t)B_DIM * D_DIM];   // normalized fp16 X
__device__ __align__(16) __half g_wh[(size_t)C_DIM * D_DIM];   // normalized fp16 W

// ---------------- helpers ----------------------------------------------------
static __device__ __forceinline__ uint32_t smem_u32(const void* p) {
    uint32_t a;
    asm("{ .reg .u64 t; cvta.to.shared.u64 t, %1; cvt.u32.u64 %0, t; }" : "=r"(a) : "l"(p));
    return a;
}
static __device__ __forceinline__ void cp16(uint32_t dst, const void* src) {
    asm volatile("cp.async.cg.shared.global [%0], [%1], 16;" :: "r"(dst), "l"(src) : "memory");
}
static __device__ __forceinline__ void ldsm_x4(uint32_t* r, uint32_t addr) {
    asm volatile("ldmatrix.sync.aligned.m8n8.x4.shared.b16 {%0,%1,%2,%3}, [%4];"
                 : "=r"(r[0]), "=r"(r[1]), "=r"(r[2]), "=r"(r[3]) : "r"(addr));
}
static __device__ __forceinline__ void mma_f16(float* d, const uint32_t* a,
                                               uint32_t b0, uint32_t b1) {
    asm volatile(
        "mma.sync.aligned.m16n8k16.row.col.f32.f16.f16.f32 "
        "{%0,%1,%2,%3}, {%4,%5,%6,%7}, {%8,%9}, {%0,%1,%2,%3};"
        : "+f"(d[0]), "+f"(d[1]), "+f"(d[2]), "+f"(d[3])
        : "r"(a[0]), "r"(a[1]), "r"(a[2]), "r"(a[3]), "r"(b0), "r"(b1));
}
static __device__ __forceinline__ uint32_t swz(uint32_t row, uint32_t quad) {
    return row * 128u + ((quad ^ (row & 7u)) << 4);
}

// ---------------- prep: L2-normalize row, emit fp16 --------------------------
// One block (128 threads) per row of 512 floats; each thread one float4.
__global__ void prep_h(const float* __restrict__ src, __half* __restrict__ dst) {
    int row = blockIdx.x;
    size_t base = (size_t)row * D_DIM + threadIdx.x * 4;
    float4 v = *reinterpret_cast<const float4*>(src + base);
    float f[4] = {v.x, v.y, v.z, v.w};

    float ss = f[0]*f[0] + f[1]*f[1] + f[2]*f[2] + f[3]*f[3];
    #pragma unroll
    for (int o = 16; o > 0; o >>= 1) ss += __shfl_xor_sync(0xffffffffu, ss, o);
    __shared__ float ws_[4], s_inv;
    int lane = threadIdx.x & 31, w = threadIdx.x >> 5;
    if (lane == 0) ws_[w] = ss;
    __syncthreads();
    if (threadIdx.x == 0)
        s_inv = 1.0f / fmaxf(sqrtf(ws_[0] + ws_[1] + ws_[2] + ws_[3]), 1e-12f);
    __syncthreads();
    float inv = s_inv;

    __half h[4];
    #pragma unroll
    for (int i = 0; i < 4; i++) h[i] = __float2half_rn(f[i] * inv);
    uint32_t lo = (uint32_t)*(uint16_t*)&h[0] | ((uint32_t)*(uint16_t*)&h[1] << 16);
    uint32_t hi = (uint32_t)*(uint16_t*)&h[2] | ((uint32_t)*(uint16_t*)&h[3] << 16);
    *reinterpret_cast<uint2*>(dst + base) = make_uint2(lo, hi);
}

// ---------------- decode targets (proven global probe) ----------------------
__global__ void decode_targets(const void* __restrict__ targets,
                               int* __restrict__ tgt) {
    const int tid = threadIdx.x;  // one block, 1024 threads
    const int* ti = reinterpret_cast<const int*>(targets);
    int odd = ti[2 * tid + 1];
    int any_nonzero = __syncthreads_or(odd != 0);
    const bool is64 = (any_nonzero == 0);
    #pragma unroll
    for (int r = 0; r < 2; r++) {
        int b = tid + r * 1024;
        int t;
        if (is64) t = (int)reinterpret_cast<const long long*>(targets)[b];
        else      t = ti[b];
        tgt[b] = t;
    }
}

// ---------------- GEMM: fp16 mma.sync, single product -----------------------
// CTA tile 128(m) x 256(n), BK = 64 halves (128B rows). 512 threads, 16 warps
// (4m x 4n), warp tile m32 x n64. 3-stage cp.async pipeline, 48KB/stage.
// smem: [0..512) targets(int) pad, [1024 + s*49152): stage s = A 16K | B 32K
#define STAGE_H 49152u
#define SMEM_H (1024u + 3u * STAGE_H)

__global__ void __launch_bounds__(512, 1)
gemm_kernel(float* __restrict__ out_loss, float* __restrict__ out_pred) {
    extern __shared__ __align__(128) unsigned char smem[];
    const uint32_t sb = smem_u32(smem);
    const uint32_t st0 = sb + 1024u;
    const int tid = threadIdx.x;
    const int wid = tid >> 5, lane = tid & 31;
    const int wm = wid & 3, wn = wid >> 2;    // 4m x 4n warp grid

    const int bid = blockIdx.x;          // m-fastest: consecutive CTAs share W panel
    const int mt = bid & 15, nt = bid >> 4;
    const int m0 = mt * 128, n0 = nt * 256;

    int* s_tg = reinterpret_cast<int*>(smem);
    if (tid < 128) s_tg[tid] = g_tgt[m0 + tid] - n0;
    __syncthreads();

    // ---- g2s issue of one K-chunk (64 halves = 128B rows) into stage s ----
    auto issue = [&](int s, int chunk) {
        uint32_t st = st0 + (uint32_t)s * STAGE_H;
        int k0 = chunk * 64;
        #pragma unroll
        for (int i = 0; i < 2; i++) {          // A: 1024 cp16
            int idx = tid + i * 512;
            uint32_t row = (uint32_t)idx >> 3, q = (uint32_t)idx & 7;
            cp16(st + swz(row, q), g_xh + ((size_t)(m0 + row) * D_DIM + k0 + q * 8));
        }
        #pragma unroll
        for (int i = 0; i < 4; i++) {          // B: 2048 cp16
            int idx = tid + i * 512;
            uint32_t row = (uint32_t)idx >> 3, q = (uint32_t)idx & 7;
            cp16(st + 16384u + swz(row, q), g_wh + ((size_t)(n0 + row) * D_DIM + k0 + q * 8));
        }
        asm volatile("cp.async.commit_group;" ::: "memory");
    };

    float acc[2][8][4];
    #pragma unroll
    for (int i = 0; i < 2; i++)
        #pragma unroll
        for (int j = 0; j < 8; j++)
            #pragma unroll
            for (int q = 0; q < 4; q++) acc[i][j][q] = 0.0f;

    issue(0, 0); issue(1, 1); issue(2, 2);

    const uint32_t arow = lane & 15;      // ldmatrix row within 16
    const uint32_t akq  = lane >> 4;      // k-quad select (0/1)

    #pragma unroll 1
    for (int c = 0; c < 8; c++) {
        if      (c <= 5) asm volatile("cp.async.wait_group 2;" ::: "memory");
        else if (c == 6) asm volatile("cp.async.wait_group 1;" ::: "memory");
        else             asm volatile("cp.async.wait_group 0;" ::: "memory");
        __syncthreads();

        uint32_t st = st0 + (uint32_t)(c % 3) * STAGE_H;
        #pragma unroll
        for (int s = 0; s < 4; s++) {     // 4 k16 steps
            uint32_t qb = 2 * s + akq;
            uint32_t ah[2][4], bh[4][4];
            #pragma unroll
            for (int mi = 0; mi < 2; mi++)
                ldsm_x4(ah[mi], st + swz((uint32_t)(wm * 32 + mi * 16) + arow, qb));
            #pragma unroll
            for (int ni = 0; ni < 4; ni++)
                ldsm_x4(bh[ni], st + 16384u + swz((uint32_t)(wn * 64 + ni * 16) + arow, qb));
            #pragma unroll
            for (int mi = 0; mi < 2; mi++)
                #pragma unroll
                for (int nb = 0; nb < 8; nb++) {
                    int ni = nb >> 1, sel = nb & 1;
                    mma_f16(acc[mi][nb], ah[mi], bh[ni][0 + sel], bh[ni][2 + sel]);
                }
        }
        __syncthreads();
        if (c + 3 < 8) issue(c % 3, c + 3);
    }

    // ---- epilogue: v = acc*32 (rows pre-normalized); fused margin ----------
    const int gr = lane >> 2, gc = lane & 3;
    #pragma unroll
    for (int mi = 0; mi < 2; mi++) {
        int rl = wm * 32 + mi * 16 + gr;      // local rows rl, rl+8
        int t0 = s_tg[rl], t1 = s_tg[rl + 8];
        size_t off0 = (size_t)(m0 + rl) * C_DIM + n0;
        size_t off1 = off0 + (size_t)8 * C_DIM;
        #pragma unroll
        for (int nb = 0; nb < 8; nb++) {
            int col = wn * 64 + nb * 8 + gc * 2;
            float2 v0 = make_float2(acc[mi][nb][0] * SCALE_F, acc[mi][nb][1] * SCALE_F);
            float2 v1 = make_float2(acc[mi][nb][2] * SCALE_F, acc[mi][nb][3] * SCALE_F);
            *reinterpret_cast<float2*>(out_pred + off0 + col) = v0;
            *reinterpret_cast<float2*>(out_pred + off1 + col) = v1;
            float2 u0 = v0, u1 = v1;
            if (t0 == col)     u0.x -= MARGIN_F;
            if (t0 == col + 1) u0.y -= MARGIN_F;
            if (t1 == col)     u1.x -= MARGIN_F;
            if (t1 == col + 1) u1.y -= MARGIN_F;
            *reinterpret_cast<float2*>(out_loss + off0 + col) = u0;
            *reinterpret_cast<float2*>(out_loss + off1 + col) = u1;
        }
    }
}

// ---------------------------------------------------------------------------
extern "C" void kernel_launch(void* const* d_in, const int* in_sizes, int n_in,
                              void* d_out, int out_size) {
    const float* x  = (const float*)d_in[0];
    const float* w  = (const float*)d_in[1];
    const void*  tg = d_in[2];

    float* out_loss = (float*)d_out;
    float* out_pred = out_loss + (size_t)B_DIM * C_DIM;

    int* tgt;
    __half *xh, *wh;
    cudaGetSymbolAddress((void**)&tgt, g_tgt);
    cudaGetSymbolAddress((void**)&xh, g_xh);
    cudaGetSymbolAddress((void**)&wh, g_wh);

    decode_targets<<<1, 1024>>>(tg, tgt);
    prep_h<<<B_DIM, 128>>>(x, xh);
    prep_h<<<C_DIM, 128>>>(w, wh);

    cudaFuncSetAttribute(gemm_kernel, cudaFuncAttributeMaxDynamicSharedMemorySize, SMEM_H);
    gemm_kernel<<<2000, 512, SMEM_H>>>(out_loss, out_pred);
}